// round 17
// baseline (speedup 1.0000x reference)
#include <cuda_runtime.h>
#include <cuda_fp16.h>
#include <cstdint>

#define HIDDEN 64
#define BATCH  4096
#define TSTEPS 9
#define DIM    512
#define GDIM   256                 // 4*HIDDEN
#define MROWS  (BATCH * TSTEPS)    // 36864

// Scratch (static device globals: allocation-guard-safe)
__device__ float  g_xg[(size_t)MROWS * GDIM];   // xg = x @ Wx + bias
__device__ __half g_wxTh[(size_t)GDIM * DIM];   // Wx^T [256][512] in fp16

// ---------------------------------------------------------------------------
// helpers
// ---------------------------------------------------------------------------
__device__ __forceinline__ void mma_f16(float c[4],
                                        unsigned a0, unsigned a1, unsigned a2, unsigned a3,
                                        unsigned b0, unsigned b1) {
    asm volatile(
        "mma.sync.aligned.m16n8k16.row.col.f32.f16.f16.f32 "
        "{%0,%1,%2,%3}, {%4,%5,%6,%7}, {%8,%9}, {%0,%1,%2,%3};"
        : "+f"(c[0]), "+f"(c[1]), "+f"(c[2]), "+f"(c[3])
        : "r"(a0), "r"(a1), "r"(a2), "r"(a3), "r"(b0), "r"(b1));
}

__device__ __forceinline__ void ldm_x4(unsigned& r0, unsigned& r1,
                                       unsigned& r2, unsigned& r3, unsigned addr) {
    asm volatile("ldmatrix.sync.aligned.m8n8.x4.shared.b16 {%0,%1,%2,%3}, [%4];"
                 : "=r"(r0), "=r"(r1), "=r"(r2), "=r"(r3) : "r"(addr));
}

__device__ __forceinline__ uint32_t smem_u32(const void* p) {
    uint32_t a;
    asm("{ .reg .u64 t; cvta.to.shared.u64 t, %1; cvt.u32.u64 %0, t; }"
        : "=r"(a) : "l"(p));
    return a;
}

__device__ __forceinline__ void cpa16(uint32_t dst, const void* src) {
    asm volatile("cp.async.cg.shared.global [%0], [%1], 16;" :: "r"(dst), "l"(src));
}
__device__ __forceinline__ void cpa_commit() { asm volatile("cp.async.commit_group;"); }
__device__ __forceinline__ void cpa_wait0()  { asm volatile("cp.async.wait_group 0;"); }

__device__ __forceinline__ unsigned pack_h2(float lo, float hi) {
    unsigned r;   // cvt.rn.f16x2.f32 d,a,b : a -> high half, b -> low half
    asm("cvt.rn.f16x2.f32 %0, %1, %2;" : "=r"(r) : "f"(hi), "f"(lo));
    return r;
}

__device__ __forceinline__ float sigm(float x)  { return 1.0f / (1.0f + __expf(-x)); }
__device__ __forceinline__ float tanhx(float x) { return 1.0f - 2.0f / (__expf(2.0f * x) + 1.0f); }

// ---------------------------------------------------------------------------
// Kernel 0: Wx^T in fp16:  g_wxTh[n][k] = half(Wx[k][n])
// Reads COALESCED over n (w natural layout); scattered 2B writes hit L2
// (output 256 KB, written once) -> latency-bound strided READS eliminated.
// ---------------------------------------------------------------------------
__global__ void wtrans(const float* __restrict__ w) {
    const int idx = blockIdx.x * 256 + threadIdx.x;   // over 512*256
    const int k = idx >> 8, n = idx & 255;
    g_wxTh[(size_t)n * DIM + k] = __float2half(w[idx]);   // w[idx]=w[k][n] coalesced
}

// ---------------------------------------------------------------------------
// Kernel 1: xg[36864,256] = x @ Wx + bias  (fp16 mma m16n8k16, fp32 accum)
// BM=64, BN=256, BK=32. 256 threads = 8 warps (2m x 4n), warp tile 32x64.
// 2 CTAs/SM (51 KB smem, <=124 regs): co-resident CTA fills barrier/staging
// bubbles. B staged via cp.async (already fp16 in gmem); A staged via
// LDG+cvt+STS. ldmatrix.x4 fragment loads. 576 CTAs ~ 1.95 waves.
// ---------------------------------------------------------------------------
#define BMg 64
#define BNg 256
#define BKg 32
#define KST 20                                   // half2 stride per row
#define STAGE ((BMg + BNg) * KST)                // 6400 unsigned per stage
#define GEMM_SMEM (2 * STAGE * 4)                // 51200 B

__global__ void __launch_bounds__(256, 2)
gemm_xg(const float* __restrict__ x, const float* __restrict__ bias) {
    extern __shared__ unsigned sm[];
    const uint32_t smb = smem_u32(sm);

    const int tid = threadIdx.x;
    const int bm  = blockIdx.x * BMg;
    const int wid = tid >> 5, lane = tid & 31;
    const int wm = wid & 1, wn = wid >> 1;
    const int lm = lane >> 3;          // ldmatrix matrix id 0..3
    const int lr = lane & 7;           // ldmatrix row-in-matrix

    // staging coords
    const int ra = tid >> 2, ca = (tid & 3) * 8;   // A: 8 floats / thread (64 rows)
    const int rb = tid;                            // B: one full 32-half row / thread

    const float* asrc = x + (size_t)(bm + ra) * DIM + ca;
    const __half* bsrc = g_wxTh + (size_t)rb * DIM;

    float4 av0, av1;

    auto LOADA = [&](int kt) {
        av0 = *(const float4*)(asrc + kt * BKg);
        av1 = *(const float4*)(asrc + kt * BKg + 4);
    };
    auto CPB = [&](int s, int kt) {
        const uint32_t bbase = smb + (uint32_t)s * (STAGE * 4)
                             + (uint32_t)(BMg * KST * 4) + (uint32_t)rb * (KST * 4);
        const __half* src = bsrc + kt * BKg;
        #pragma unroll
        for (int c = 0; c < 4; c++)
            cpa16(bbase + c * 16, src + c * 8);
        cpa_commit();
    };
    auto STOREA = [&](int s) {
        unsigned* As2 = sm + s * STAGE;
        uint4 ah;
        ah.x = pack_h2(av0.x, av0.y);
        ah.y = pack_h2(av0.z, av0.w);
        ah.z = pack_h2(av1.x, av1.y);
        ah.w = pack_h2(av1.z, av1.w);
        *(uint4*)(As2 + ra * KST + ca / 2) = ah;
    };

    float acc[2][8][4];
    #pragma unroll
    for (int i = 0; i < 2; i++)
        #pragma unroll
        for (int j = 0; j < 8; j++)
            #pragma unroll
            for (int k = 0; k < 4; k++) acc[i][j][k] = 0.0f;

    // per-lane ldmatrix base offsets (bytes)
    const uint32_t a_lane_off = (uint32_t)(wm * 32 + (lm & 1) * 8 + lr) * (KST * 4)
                              + (uint32_t)(lm >> 1) * 16;
    const uint32_t b_lane_off = (uint32_t)(BMg * KST * 4)
                              + (uint32_t)(wn * 64 + (lm >> 1) * 8 + lr) * (KST * 4)
                              + (uint32_t)(lm & 1) * 16;

    auto COMPUTE = [&](int s) {
        const uint32_t sb = smb + (uint32_t)s * (STAGE * 4);
        #pragma unroll
        for (int ks = 0; ks < 2; ks++) {
            const uint32_t kofs = (uint32_t)ks * 32;   // 16 halves = 32 B
            unsigned af[2][4];
            #pragma unroll
            for (int mi = 0; mi < 2; mi++)
                ldm_x4(af[mi][0], af[mi][1], af[mi][2], af[mi][3],
                       sb + a_lane_off + (uint32_t)mi * 16 * (KST * 4) + kofs);
            unsigned bf[8][2];
            #pragma unroll
            for (int np = 0; np < 4; np++)
                ldm_x4(bf[2 * np][0], bf[2 * np][1], bf[2 * np + 1][0], bf[2 * np + 1][1],
                       sb + b_lane_off + (uint32_t)np * 16 * (KST * 4) + kofs);
            #pragma unroll
            for (int ni = 0; ni < 8; ni++)
                #pragma unroll
                for (int mi = 0; mi < 2; mi++)
                    mma_f16(acc[mi][ni], af[mi][0], af[mi][1], af[mi][2], af[mi][3],
                            bf[ni][0], bf[ni][1]);
        }
    };

    // prologue: stage 0
    LOADA(0); CPB(0, 0);
    STOREA(0);
    cpa_wait0();
    __syncthreads();

    #pragma unroll 1
    for (int kt = 1; kt < DIM / BKg; kt++) {
        LOADA(kt); CPB(kt & 1, kt);      // latency hides under COMPUTE
        COMPUTE((kt - 1) & 1);
        STOREA(kt & 1);
        cpa_wait0();                     // stage kt&1 B complete
        __syncthreads();                 // visible CTA-wide
    }
    COMPUTE(1);                          // (DIM/BKg - 1) & 1 == 1

    // epilogue: natural layout xg[row][col] + bias
    const int grp = lane >> 2, tig = lane & 3;
    #pragma unroll
    for (int mi = 0; mi < 2; mi++) {
        #pragma unroll
        for (int ni = 0; ni < 8; ni++) {
            const int row = bm + wm * 32 + mi * 16 + grp;
            const int col = wn * 64 + ni * 8 + tig * 2;
            const float bb0 = bias[col], bb1 = bias[col + 1];
            g_xg[(size_t)row * GDIM + col]           = acc[mi][ni][0] + bb0;
            g_xg[(size_t)row * GDIM + col + 1]       = acc[mi][ni][1] + bb1;
            g_xg[(size_t)(row + 8) * GDIM + col]     = acc[mi][ni][2] + bb0;
            g_xg[(size_t)(row + 8) * GDIM + col + 1] = acc[mi][ni][3] + bb1;
        }
    }
}

// ---------------------------------------------------------------------------
// Kernel 2: TENSOR-CORE LSTM scan (round-14 WIN — unchanged).
// ---------------------------------------------------------------------------
#define SC_NB 16
#define WS2 36
#define HS2 36
#define GST 264
#define SCAN_SMEM (256 * WS2 * 4 + SC_NB * HS2 * 4 + SC_NB * GST * 4)  // 56064 B

__global__ void __launch_bounds__(256, 2)
lstm_scan(const float* __restrict__ w, float* __restrict__ out) {
    extern __shared__ unsigned smu[];
    unsigned* Whs = smu;                          // [256][WS2] half2
    unsigned* hs2 = smu + 256 * WS2;              // [16][HS2] half2
    float*    gmat = (float*)(smu + 256 * WS2 + SC_NB * HS2);  // [16][GST]

    const int tid  = threadIdx.x;
    const int lane = tid & 31;
    const int wn   = tid >> 5;
    const int l4   = lane >> 2;
    const int l2   = lane & 3;
    const int h    = tid & 63;
    const int bq   = tid >> 6;
    const int bbase = blockIdx.x * SC_NB;

    for (int idx = tid; idx < 64 * 256; idx += 256) {
        const int k = idx >> 8, n = idx & 255;
        ((__half*)Whs)[n * (2 * WS2) + k] = __float2half(w[(size_t)(DIM + k) * GDIM + n]);
    }
    __syncthreads();

    unsigned bf[4][4][2];
    #pragma unroll
    for (int kc = 0; kc < 4; kc++)
        #pragma unroll
        for (int ni = 0; ni < 4; ni++) {
            const int col = wn * 32 + ni * 8 + l4;
            bf[kc][ni][0] = Whs[col * WS2 + kc * 8 + l2];
            bf[kc][ni][1] = Whs[col * WS2 + kc * 8 + l2 + 4];
        }

    float c[4];
    #pragma unroll
    for (int j = 0; j < 4; j++) c[j] = 0.0f;

    float pre[4][4];
    auto PREF = [&](int t) {
        #pragma unroll
        for (int ni = 0; ni < 4; ni++) {
            const int col = wn * 32 + ni * 8 + 2 * l2;
            const float2 v0 = *(const float2*)(g_xg +
                ((size_t)(bbase + l4) * TSTEPS + t) * GDIM + col);
            const float2 v1 = *(const float2*)(g_xg +
                ((size_t)(bbase + l4 + 8) * TSTEPS + t) * GDIM + col);
            pre[ni][0] = v0.x; pre[ni][1] = v0.y;
            pre[ni][2] = v1.x; pre[ni][3] = v1.y;
        }
    };

    PREF(0);

    #pragma unroll 1
    for (int t = 0; t < TSTEPS; t++) {
        float acc[4][4];
        #pragma unroll
        for (int ni = 0; ni < 4; ni++)
            #pragma unroll
            for (int q = 0; q < 4; q++) acc[ni][q] = pre[ni][q];

        if (t + 1 < TSTEPS) PREF(t + 1);

        if (t > 0) {
            #pragma unroll
            for (int kc = 0; kc < 4; kc++) {
                const unsigned a0 = hs2[l4 * HS2 + kc * 8 + l2];
                const unsigned a1 = hs2[(l4 + 8) * HS2 + kc * 8 + l2];
                const unsigned a2 = hs2[l4 * HS2 + kc * 8 + l2 + 4];
                const unsigned a3 = hs2[(l4 + 8) * HS2 + kc * 8 + l2 + 4];
                #pragma unroll
                for (int ni = 0; ni < 4; ni++)
                    mma_f16(acc[ni], a0, a1, a2, a3, bf[kc][ni][0], bf[kc][ni][1]);
            }
        }

        #pragma unroll
        for (int ni = 0; ni < 4; ni++) {
            const int col = wn * 32 + ni * 8 + 2 * l2;
            *(float2*)(gmat + l4 * GST + col)       = make_float2(acc[ni][0], acc[ni][1]);
            *(float2*)(gmat + (l4 + 8) * GST + col) = make_float2(acc[ni][2], acc[ni][3]);
        }
        __syncthreads();

        #pragma unroll
        for (int j = 0; j < 4; j++) {
            const int b = bq * 4 + j;
            const float gi = gmat[b * GST + h];
            const float gj = gmat[b * GST + 64 + h];
            const float gf = gmat[b * GST + 128 + h];
            const float go = gmat[b * GST + 192 + h];

            const float ig = sigm(gi);
            const float jg = tanhx(gj);
            const float fg = sigm(gf + 1.0f);        // FORGET_BIAS
            const float og = sigm(go);
            const float cn = fg * c[j] + ig * jg;
            c[j] = cn;
            const float hn = og * tanhx(cn);

            ((__half*)hs2)[b * (2 * HS2) + h] = __float2half(hn);
            out[((size_t)(bbase + b) * TSTEPS + t) * HIDDEN + h] = hn;
        }
        __syncthreads();
    }
}

// ---------------------------------------------------------------------------
extern "C" void kernel_launch(void* const* d_in, const int* in_sizes, int n_in,
                              void* d_out, int out_size) {
    const float* x    = (const float*)d_in[0];
    const float* w    = (const float*)d_in[1];
    const float* bias = (const float*)d_in[2];
    float* out        = (float*)d_out;
    (void)in_sizes; (void)n_in; (void)out_size;

    wtrans<<<GDIM * DIM / 256, 256>>>(w);

    cudaFuncSetAttribute(gemm_xg, cudaFuncAttributeMaxDynamicSharedMemorySize, GEMM_SMEM);
    gemm_xg<<<MROWS / BMg, 256, GEMM_SMEM>>>(x, bias);

    cudaFuncSetAttribute(lstm_scan, cudaFuncAttributeMaxDynamicSharedMemorySize, SCAN_SMEM);
    lstm_scan<<<BATCH / SC_NB, 256, SCAN_SMEM>>>(w, out);
}